// round 14
// baseline (speedup 1.0000x reference)
#include <cuda_runtime.h>
#include <cuda_bf16.h>
#include <math.h>
#include <stdint.h>

#define K_COMP 64
#define DDIM   256
#define MU_PAD 264     // bf16/row: 132 words -> ldmatrix rows cover all 32 banks

// ---------------- fast exp: FFMA-only (no MUFU; clamp keeps i<<23 in range) ----------
__device__ __forceinline__ float fexp(float x) {
    x = fmaxf(x, -87.0f);
    float z = x * 1.4426950408889634f;
    float t = z + 12582912.0f;
    float fi = t - 12582912.0f;
    float f = z - fi;
    int  i  = __float_as_int(t) - 0x4B400000;
    float p = 1.3333558e-3f;
    p = fmaf(p, f, 9.6181291e-3f);
    p = fmaf(p, f, 5.5504109e-2f);
    p = fmaf(p, f, 2.4022651e-1f);
    p = fmaf(p, f, 6.9314718e-1f);
    p = fmaf(p, f, 1.0f);
    return __int_as_float(__float_as_int(p) + (i << 23));
}

__device__ __forceinline__ uint32_t f22bf(float2 v) {
    __nv_bfloat162 b = __float22bfloat162_rn(v);
    return *reinterpret_cast<uint32_t*>(&b);
}

// ---------------- single fused kernel ---------------------------------------------
// Prologue: stage RAW mu (bf16, k-pair-permuted) — no normalization needed because
// 1/||mu|| is folded into kappa' (kappa*(x·mu_hat) == (kappa/||mu||)*(x·mu_raw)).
// Norms are computed from the staged bf16 tile (permutation-invariant), the Bessel
// series uses FFMA fexp (MUFU-free). All prep regs are dead before the mainloop.
// Mainloop + epilogue are byte-identical to R10 (the 69.7us champion).
__global__ void __launch_bounds__(256, 2)
vmf_main(const float* __restrict__ x,
         const float* __restrict__ alpha_logit,
         const float* __restrict__ mu_unnorm,
         const float* __restrict__ log_kappa,
         float* __restrict__ out_llh,
         float* __restrict__ out_lp,
         int N) {
    __shared__ __align__(16) __nv_bfloat16 smu[K_COMP][MU_PAD];
    __shared__ float s_kappa[K_COMP], s_logC[K_COMP], s_la[K_COMP], s_C2[K_COMP];
    __shared__ float s_cm[K_COMP], s_sa[K_COMP], s_lk[K_COMP];

    int tid = threadIdx.x, warp = tid >> 5, lane = tid & 31;

    // ---- stage RAW mu with k-pair permutation (slot i <- phys pair (i<4 ? 2i : 2i-7))
    const float2* gmu2 = reinterpret_cast<const float2*>(mu_unnorm);
    for (int idx = tid; idx < K_COMP * (DDIM / 2); idx += 256) {
        int kk = idx >> 7;
        int dp = idx & 127;
        int i  = dp & 7;
        int srcp = (i < 4) ? (2 * i) : (2 * i - 7);
        int src  = (dp & ~7) | srcp;
        float2 v = gmu2[kk * 128 + src];
        reinterpret_cast<__nv_bfloat162*>(&smu[kk][0])[dp] = __float22bfloat162_rn(v);
    }
    if (tid < K_COMP) {
        s_cm[tid] = lgammaf((float)tid + 1.0f) + lgammaf((float)tid + 128.0f);
        s_sa[tid] = alpha_logit[tid];
        s_lk[tid] = log_kappa[tid];
    }
    __syncthreads();

    // ---- per-CTA constants: warp w handles comps k = w*8 + rr ----
    {
        const float s = 127.0f;
        // log-softmax denominator (each warp computes it redundantly; cheap)
        float a0 = s_sa[lane], a1 = s_sa[lane + 32];
        float am = fmaxf(a0, a1);
#pragma unroll
        for (int o = 16; o; o >>= 1) am = fmaxf(am, __shfl_xor_sync(0xffffffffu, am, o));
        float ae = fexp(a0 - am) + fexp(a1 - am);
#pragma unroll
        for (int o = 16; o; o >>= 1) ae += __shfl_xor_sync(0xffffffffu, ae, o);
        float lse = am + __logf(ae);

#pragma unroll
        for (int rr = 0; rr < 8; rr++) {
            int k = warp * 8 + rr;
            // ||mu_bf16||: read staged row (permutation-invariant sum of squares)
            float4 q = reinterpret_cast<const float4*>(&smu[k][0])[lane];
            const __nv_bfloat162* qb = reinterpret_cast<const __nv_bfloat162*>(&q);
            float ss = 0.0f;
#pragma unroll
            for (int j = 0; j < 4; j++) {
                float2 f = __bfloat1622float2(qb[j]);
                ss = fmaf(f.x, f.x, fmaf(f.y, f.y, ss));
            }
#pragma unroll
            for (int o = 16; o; o >>= 1) ss += __shfl_xor_sync(0xffffffffu, ss, o);

            // log I_s(kappa) via 64-term series (FFMA fexp), warp-reduced logsumexp
            float kap = fexp(s_lk[k]) + 1e-6f;
            float lk2 = __logf(0.5f * kap);
            float t0 = fmaf(2.0f * lane + s,        lk2, -s_cm[lane]);
            float t1 = fmaf(2.0f * (lane + 32) + s, lk2, -s_cm[lane + 32]);
            float tm = fmaxf(t0, t1);
#pragma unroll
            for (int o = 16; o; o >>= 1) tm = fmaxf(tm, __shfl_xor_sync(0xffffffffu, tm, o));
            float ts = fexp(t0 - tm) + fexp(t1 - tm);
#pragma unroll
            for (int o = 16; o; o >>= 1) ts += __shfl_xor_sync(0xffffffffu, ts, o);

            if (lane == 0) {
                float lbi  = tm + __logf(ts);
                float logC = 256.0f * (-0.91893853320467274f) + s * __logf(kap) - lbi;
                float nrm  = fmaxf(sqrtf(ss), 1e-12f);
                float la   = s_sa[k] - lse;
                s_kappa[k] = kap / nrm;      // kappa' — norm folded
                s_logC[k]  = logC;
                s_la[k]    = la;
                s_C2[k]    = logC + la;
            }
        }
    }
    __syncthreads();

    // ================= mainloop: identical to R10 =================
    int row0 = blockIdx.x * 256 + warp * 32;   // 32 rows per warp
    int r  = lane >> 2;        // 0..7
    int cq = (lane & 3) * 2;   // logical col-pair base (epilogue)

    const float* p0 = x + (size_t)(row0 + r) * DDIM + (lane & 3) * 4;

    uint32_t smu_base = (uint32_t)__cvta_generic_to_shared(&smu[0][0]);
    int li   = lane & 7;
    int csel = (lane >> 3) & 1;
    int tsel = (lane >> 4) & 1;
    uint32_t lm_base = smu_base + (uint32_t)(((li + tsel * 8) * MU_PAD + csel * 8) * 2);

    float acc0[8][4], acc1[8][4];
#pragma unroll
    for (int t = 0; t < 8; t++)
#pragma unroll
        for (int j = 0; j < 4; j++) { acc0[t][j] = 0.0f; acc1[t][j] = 0.0f; }

    float4 buf[2][4];
#pragma unroll
    for (int c = 0; c < 2; c++)
#pragma unroll
        for (int g = 0; g < 4; g++)
            buf[c][g] = __ldcs(reinterpret_cast<const float4*>(p0 + c * 16 + g * 8 * DDIM));

#pragma unroll
    for (int kk = 0; kk < 16; kk++) {
        int b = kk & 1;
        float4 A0 = buf[b][0], A1 = buf[b][1], A2 = buf[b][2], A3 = buf[b][3];

        uint32_t u0 = f22bf(make_float2(A0.x, A0.y));
        uint32_t u1 = f22bf(make_float2(A1.x, A1.y));
        uint32_t u2 = f22bf(make_float2(A0.z, A0.w));
        uint32_t u3 = f22bf(make_float2(A1.z, A1.w));
        uint32_t v0 = f22bf(make_float2(A2.x, A2.y));
        uint32_t v1 = f22bf(make_float2(A3.x, A3.y));
        uint32_t v2 = f22bf(make_float2(A2.z, A2.w));
        uint32_t v3 = f22bf(make_float2(A3.z, A3.w));

        if (kk < 14) {
            int off = (kk + 2) * 16;
#pragma unroll
            for (int g = 0; g < 4; g++)
                buf[b][g] = __ldcs(reinterpret_cast<const float4*>(p0 + off + g * 8 * DDIM));
        }

        uint32_t lmaddr = lm_base + (uint32_t)(kk * 32);
#pragma unroll
        for (int tp = 0; tp < 4; tp++) {
            uint32_t b0, b1, b2, b3;
            asm volatile(
                "ldmatrix.sync.aligned.m8n8.x4.shared.b16 {%0,%1,%2,%3}, [%4];\n"
                : "=r"(b0), "=r"(b1), "=r"(b2), "=r"(b3)
                : "r"(lmaddr + (uint32_t)(tp * 16 * MU_PAD * 2)));
            asm volatile(
                "mma.sync.aligned.m16n8k16.row.col.f32.bf16.bf16.f32 "
                "{%0,%1,%2,%3}, {%4,%5,%6,%7}, {%8,%9}, {%0,%1,%2,%3};\n"
                : "+f"(acc0[tp*2][0]), "+f"(acc0[tp*2][1]), "+f"(acc0[tp*2][2]), "+f"(acc0[tp*2][3])
                : "r"(u0), "r"(u1), "r"(u2), "r"(u3), "r"(b0), "r"(b1));
            asm volatile(
                "mma.sync.aligned.m16n8k16.row.col.f32.bf16.bf16.f32 "
                "{%0,%1,%2,%3}, {%4,%5,%6,%7}, {%8,%9}, {%0,%1,%2,%3};\n"
                : "+f"(acc0[tp*2+1][0]), "+f"(acc0[tp*2+1][1]), "+f"(acc0[tp*2+1][2]), "+f"(acc0[tp*2+1][3])
                : "r"(u0), "r"(u1), "r"(u2), "r"(u3), "r"(b2), "r"(b3));
            asm volatile(
                "mma.sync.aligned.m16n8k16.row.col.f32.bf16.bf16.f32 "
                "{%0,%1,%2,%3}, {%4,%5,%6,%7}, {%8,%9}, {%0,%1,%2,%3};\n"
                : "+f"(acc1[tp*2][0]), "+f"(acc1[tp*2][1]), "+f"(acc1[tp*2][2]), "+f"(acc1[tp*2][3])
                : "r"(v0), "r"(v1), "r"(v2), "r"(v3), "r"(b0), "r"(b1));
            asm volatile(
                "mma.sync.aligned.m16n8k16.row.col.f32.bf16.bf16.f32 "
                "{%0,%1,%2,%3}, {%4,%5,%6,%7}, {%8,%9}, {%0,%1,%2,%3};\n"
                : "+f"(acc1[tp*2+1][0]), "+f"(acc1[tp*2+1][1]), "+f"(acc1[tp*2+1][2]), "+f"(acc1[tp*2+1][3])
                : "r"(v0), "r"(v1), "r"(v2), "r"(v3), "r"(b2), "r"(b3));
        }
    }

    // ---- epilogue: two row-groups (kappa' already includes 1/||mu||) ----
#pragma unroll
    for (int G = 0; G < 2; G++) {
        int gr0 = row0 + G * 16 + r, gr1 = gr0 + 8;
        float2* lp0 = reinterpret_cast<float2*>(out_lp + (size_t)gr0 * K_COMP);
        float2* lp1 = reinterpret_cast<float2*>(out_lp + (size_t)gr1 * K_COMP);

        float m0 = -1e30f, m1 = -1e30f;
#pragma unroll
        for (int t = 0; t < 8; t++) {
            int cc = t * 8 + cq;
            float a0 = G ? acc1[t][0] : acc0[t][0];
            float a1 = G ? acc1[t][1] : acc0[t][1];
            float a2 = G ? acc1[t][2] : acc0[t][2];
            float a3 = G ? acc1[t][3] : acc0[t][3];
            float k0 = s_kappa[cc], k1 = s_kappa[cc + 1];
            float lc0 = s_logC[cc], lc1 = s_logC[cc + 1];
            float la0 = s_la[cc],   la1 = s_la[cc + 1];
            float lp00 = fmaf(k0, a0, lc0);
            float lp01 = fmaf(k1, a1, lc1);
            float lp10 = fmaf(k0, a2, lc0);
            float lp11 = fmaf(k1, a3, lc1);
            __stcs(lp0 + (cc >> 1), make_float2(lp00, lp01));
            __stcs(lp1 + (cc >> 1), make_float2(lp10, lp11));
            m0 = fmaxf(m0, fmaxf(lp00 + la0, lp01 + la1));
            m1 = fmaxf(m1, fmaxf(lp10 + la0, lp11 + la1));
        }
        m0 = fmaxf(m0, __shfl_xor_sync(0xffffffffu, m0, 1));
        m0 = fmaxf(m0, __shfl_xor_sync(0xffffffffu, m0, 2));
        m1 = fmaxf(m1, __shfl_xor_sync(0xffffffffu, m1, 1));
        m1 = fmaxf(m1, __shfl_xor_sync(0xffffffffu, m1, 2));

        float s0 = 0.0f, s1 = 0.0f;
#pragma unroll
        for (int t = 0; t < 8; t++) {
            int cc = t * 8 + cq;
            float a0 = G ? acc1[t][0] : acc0[t][0];
            float a1 = G ? acc1[t][1] : acc0[t][1];
            float a2 = G ? acc1[t][2] : acc0[t][2];
            float a3 = G ? acc1[t][3] : acc0[t][3];
            float k0 = s_kappa[cc], k1 = s_kappa[cc + 1];
            float c20 = s_C2[cc],   c21 = s_C2[cc + 1];
            s0 += fexp(fmaf(k0, a0, c20) - m0);
            s0 += fexp(fmaf(k1, a1, c21) - m0);
            s1 += fexp(fmaf(k0, a2, c20) - m1);
            s1 += fexp(fmaf(k1, a3, c21) - m1);
        }
        s0 += __shfl_xor_sync(0xffffffffu, s0, 1);
        s0 += __shfl_xor_sync(0xffffffffu, s0, 2);
        s1 += __shfl_xor_sync(0xffffffffu, s1, 1);
        s1 += __shfl_xor_sync(0xffffffffu, s1, 2);

        if ((lane & 3) == 0) {
            out_llh[gr0] = m0 + __logf(s0);
            out_llh[gr1] = m1 + __logf(s1);
        }
    }
}

// ---------------- launch: ONE kernel, no prep ---------------------------------------
extern "C" void kernel_launch(void* const* d_in, const int* in_sizes, int n_in,
                              void* d_out, int out_size) {
    const float* x           = (const float*)d_in[0];
    const float* alpha_logit = (const float*)d_in[1];
    const float* mu_unnorm   = (const float*)d_in[2];
    const float* log_kappa   = (const float*)d_in[3];

    int K = in_sizes[1];            // 64
    int D = in_sizes[2] / K;        // 256
    int N = in_sizes[0] / D;        // 262144
    (void)n_in; (void)out_size;

    float* out = (float*)d_out;
    float* llh = out;               // (N,)
    float* lp  = out + (size_t)N;   // (N, K)

    vmf_main<<<N / 256, 256>>>(x, alpha_logit, mu_unnorm, log_kappa, llh, lp, N);
}

// round 15
// speedup vs baseline: 1.1409x; 1.1409x over previous
#include <cuda_runtime.h>
#include <cuda_bf16.h>
#include <math.h>
#include <stdint.h>

#define K_COMP 64
#define DDIM   256
#define MU_PAD 264     // bf16/row: 132 words -> ldmatrix rows cover all 32 banks

__device__ __align__(16) __nv_bfloat16 g_mu[K_COMP * DDIM];
__device__ float g_kappa[K_COMP];
__device__ float g_logC[K_COMP];
__device__ float g_la[K_COMP];
__device__ float g_C2[K_COMP];

// ---------------- prep: 64 blocks (one per component); triggers PDL at end ------------
__global__ void prep_fast(const float* __restrict__ alpha_logit,
                          const float* __restrict__ mu_unnorm,
                          const float* __restrict__ log_kappa) {
    __shared__ float sred[4];
    int k = blockIdx.x;
    int tid = threadIdx.x, lane = tid & 31, w = tid >> 5;
    const float s = 0.5f * (float)DDIM - 1.0f;   // 127

    float2 v = reinterpret_cast<const float2*>(mu_unnorm + (size_t)k * DDIM)[tid];
    float ss = v.x * v.x + v.y * v.y;
#pragma unroll
    for (int o = 16; o; o >>= 1) ss += __shfl_xor_sync(0xffffffffu, ss, o);
    if (lane == 0) sred[w] = ss;
    __syncthreads();
    float tot = sred[0] + sred[1] + sred[2] + sred[3];
    float inv = 1.0f / fmaxf(sqrtf(tot), 1e-12f);
    reinterpret_cast<__nv_bfloat162*>(g_mu + (size_t)k * DDIM)[tid] =
        __float22bfloat162_rn(make_float2(v.x * inv, v.y * inv));

    if (w == 0) {
        float a0 = alpha_logit[lane], a1 = alpha_logit[lane + 32];
        float am = fmaxf(a0, a1);
#pragma unroll
        for (int o = 16; o; o >>= 1) am = fmaxf(am, __shfl_xor_sync(0xffffffffu, am, o));
        float ae = expf(a0 - am) + expf(a1 - am);
#pragma unroll
        for (int o = 16; o; o >>= 1) ae += __shfl_xor_sync(0xffffffffu, ae, o);
        float lse = am + logf(ae);

        float kap = expf(log_kappa[k]) + 1e-6f;
        float lk2 = logf(0.5f * kap);
        float cm0 = lgammaf((float)lane + 1.0f)  + lgammaf((float)lane + s + 1.0f);
        float cm1 = lgammaf((float)lane + 33.0f) + lgammaf((float)lane + s + 33.0f);
        float t0 = fmaf(2.0f * lane + s,        lk2, -cm0);
        float t1 = fmaf(2.0f * (lane + 32) + s, lk2, -cm1);
        float tm = fmaxf(t0, t1);
#pragma unroll
        for (int o = 16; o; o >>= 1) tm = fmaxf(tm, __shfl_xor_sync(0xffffffffu, tm, o));
        float ts = expf(t0 - tm) + expf(t1 - tm);
#pragma unroll
        for (int o = 16; o; o >>= 1) ts += __shfl_xor_sync(0xffffffffu, ts, o);

        if (lane == 0) {
            float lbi  = tm + logf(ts);
            float logC = (float)DDIM * (-0.91893853320467274f) + s * logf(kap) - lbi;
            float la   = alpha_logit[k] - lse;
            g_kappa[k] = kap;
            g_logC[k]  = logC;
            g_la[k]    = la;
            g_C2[k]    = logC + la;
        }
    }
    __syncthreads();   // all writes done before trigger
    cudaTriggerProgrammaticLaunchCompletion();
}

// ---------------- fast exp: FFMA-only ----------------
__device__ __forceinline__ float fexp(float x) {
    x = fmaxf(x, -87.0f);
    float z = x * 1.4426950408889634f;
    float t = z + 12582912.0f;
    float fi = t - 12582912.0f;
    float f = z - fi;
    int  i  = __float_as_int(t) - 0x4B400000;
    float p = 1.3333558e-3f;
    p = fmaf(p, f, 9.6181291e-3f);
    p = fmaf(p, f, 5.5504109e-2f);
    p = fmaf(p, f, 2.4022651e-1f);
    p = fmaf(p, f, 6.9314718e-1f);
    p = fmaf(p, f, 1.0f);
    return __int_as_float(__float_as_int(p) + (i << 23));
}

__device__ __forceinline__ uint32_t f22bf(float2 v) {
    __nv_bfloat162 b = __float22bfloat162_rn(v);
    return *reinterpret_cast<uint32_t*>(&b);
}

// ---------------- main: R10 champion (32 rows/warp) + PDL grid-dependency sync --------
__global__ void __launch_bounds__(256, 2)
vmf_main(const float* __restrict__ x,
         float* __restrict__ out_llh,
         float* __restrict__ out_lp,
         int N) {
    __shared__ __align__(16) __nv_bfloat16 smu[K_COMP][MU_PAD];
    __shared__ float s_kappa[K_COMP], s_logC[K_COMP], s_la[K_COMP], s_C2[K_COMP];

    int tid = threadIdx.x;
    int warp = tid >> 5, lane = tid & 31;
    int row0 = blockIdx.x * 256 + warp * 32;   // 32 rows per warp
    int r  = lane >> 2;        // 0..7
    int cq = (lane & 3) * 2;   // logical col-pair base (epilogue)

    const float* p0 = x + (size_t)(row0 + r) * DDIM + (lane & 3) * 4;

    uint32_t smu_base = (uint32_t)__cvta_generic_to_shared(&smu[0][0]);
    int li   = lane & 7;
    int csel = (lane >> 3) & 1;
    int tsel = (lane >> 4) & 1;
    uint32_t lm_base = smu_base + (uint32_t)(((li + tsel * 8) * MU_PAD + csel * 8) * 2);

    // wait for prep's g_* writes (overlapped launch via PDL)
    cudaGridDependencySynchronize();

    // stage mu with k-pair permutation (slot i <- phys pair (i<4 ? 2i : 2i-7))
    const uint32_t* gmu32 = reinterpret_cast<const uint32_t*>(g_mu);
    for (int idx = tid; idx < K_COMP * (DDIM / 2); idx += 256) {
        int kk = idx >> 7;
        int dp = idx & 127;
        int i  = dp & 7;
        int srcp = (i < 4) ? (2 * i) : (2 * i - 7);
        int src  = (dp & ~7) | srcp;
        reinterpret_cast<uint32_t*>(&smu[kk][0])[dp] = gmu32[kk * 128 + src];
    }
    if (tid < K_COMP) {
        s_kappa[tid] = g_kappa[tid];
        s_logC[tid]  = g_logC[tid];
        s_la[tid]    = g_la[tid];
        s_C2[tid]    = g_C2[tid];
    }
    __syncthreads();

    float acc0[8][4], acc1[8][4];
#pragma unroll
    for (int t = 0; t < 8; t++)
#pragma unroll
        for (int j = 0; j < 4; j++) { acc0[t][j] = 0.0f; acc1[t][j] = 0.0f; }

    // 2-buffer depth-2 prefetch; buf[b][g] = rows r + 8g
    float4 buf[2][4];
#pragma unroll
    for (int c = 0; c < 2; c++)
#pragma unroll
        for (int g = 0; g < 4; g++)
            buf[c][g] = __ldcs(reinterpret_cast<const float4*>(p0 + c * 16 + g * 8 * DDIM));

#pragma unroll
    for (int kk = 0; kk < 16; kk++) {
        int b = kk & 1;
        float4 A0 = buf[b][0], A1 = buf[b][1], A2 = buf[b][2], A3 = buf[b][3];

        uint32_t u0 = f22bf(make_float2(A0.x, A0.y));
        uint32_t u1 = f22bf(make_float2(A1.x, A1.y));
        uint32_t u2 = f22bf(make_float2(A0.z, A0.w));
        uint32_t u3 = f22bf(make_float2(A1.z, A1.w));
        uint32_t v0 = f22bf(make_float2(A2.x, A2.y));
        uint32_t v1 = f22bf(make_float2(A3.x, A3.y));
        uint32_t v2 = f22bf(make_float2(A2.z, A2.w));
        uint32_t v3 = f22bf(make_float2(A3.z, A3.w));

        if (kk < 14) {
            int off = (kk + 2) * 16;
#pragma unroll
            for (int g = 0; g < 4; g++)
                buf[b][g] = __ldcs(reinterpret_cast<const float4*>(p0 + off + g * 8 * DDIM));
        }

        uint32_t lmaddr = lm_base + (uint32_t)(kk * 32);
#pragma unroll
        for (int tp = 0; tp < 4; tp++) {
            uint32_t b0, b1, b2, b3;
            asm volatile(
                "ldmatrix.sync.aligned.m8n8.x4.shared.b16 {%0,%1,%2,%3}, [%4];\n"
                : "=r"(b0), "=r"(b1), "=r"(b2), "=r"(b3)
                : "r"(lmaddr + (uint32_t)(tp * 16 * MU_PAD * 2)));
            asm volatile(
                "mma.sync.aligned.m16n8k16.row.col.f32.bf16.bf16.f32 "
                "{%0,%1,%2,%3}, {%4,%5,%6,%7}, {%8,%9}, {%0,%1,%2,%3};\n"
                : "+f"(acc0[tp*2][0]), "+f"(acc0[tp*2][1]), "+f"(acc0[tp*2][2]), "+f"(acc0[tp*2][3])
                : "r"(u0), "r"(u1), "r"(u2), "r"(u3), "r"(b0), "r"(b1));
            asm volatile(
                "mma.sync.aligned.m16n8k16.row.col.f32.bf16.bf16.f32 "
                "{%0,%1,%2,%3}, {%4,%5,%6,%7}, {%8,%9}, {%0,%1,%2,%3};\n"
                : "+f"(acc0[tp*2+1][0]), "+f"(acc0[tp*2+1][1]), "+f"(acc0[tp*2+1][2]), "+f"(acc0[tp*2+1][3])
                : "r"(u0), "r"(u1), "r"(u2), "r"(u3), "r"(b2), "r"(b3));
            asm volatile(
                "mma.sync.aligned.m16n8k16.row.col.f32.bf16.bf16.f32 "
                "{%0,%1,%2,%3}, {%4,%5,%6,%7}, {%8,%9}, {%0,%1,%2,%3};\n"
                : "+f"(acc1[tp*2][0]), "+f"(acc1[tp*2][1]), "+f"(acc1[tp*2][2]), "+f"(acc1[tp*2][3])
                : "r"(v0), "r"(v1), "r"(v2), "r"(v3), "r"(b0), "r"(b1));
            asm volatile(
                "mma.sync.aligned.m16n8k16.row.col.f32.bf16.bf16.f32 "
                "{%0,%1,%2,%3}, {%4,%5,%6,%7}, {%8,%9}, {%0,%1,%2,%3};\n"
                : "+f"(acc1[tp*2+1][0]), "+f"(acc1[tp*2+1][1]), "+f"(acc1[tp*2+1][2]), "+f"(acc1[tp*2+1][3])
                : "r"(v0), "r"(v1), "r"(v2), "r"(v3), "r"(b2), "r"(b3));
        }
    }

    // ---- epilogue: two row-groups, R4 form each ----
#pragma unroll
    for (int G = 0; G < 2; G++) {
        int gr0 = row0 + G * 16 + r, gr1 = gr0 + 8;
        float2* lp0 = reinterpret_cast<float2*>(out_lp + (size_t)gr0 * K_COMP);
        float2* lp1 = reinterpret_cast<float2*>(out_lp + (size_t)gr1 * K_COMP);

        float m0 = -1e30f, m1 = -1e30f;
#pragma unroll
        for (int t = 0; t < 8; t++) {
            int cc = t * 8 + cq;
            float a0 = G ? acc1[t][0] : acc0[t][0];
            float a1 = G ? acc1[t][1] : acc0[t][1];
            float a2 = G ? acc1[t][2] : acc0[t][2];
            float a3 = G ? acc1[t][3] : acc0[t][3];
            float k0 = s_kappa[cc], k1 = s_kappa[cc + 1];
            float lc0 = s_logC[cc], lc1 = s_logC[cc + 1];
            float la0 = s_la[cc],   la1 = s_la[cc + 1];
            float lp00 = fmaf(k0, a0, lc0);
            float lp01 = fmaf(k1, a1, lc1);
            float lp10 = fmaf(k0, a2, lc0);
            float lp11 = fmaf(k1, a3, lc1);
            __stcs(lp0 + (cc >> 1), make_float2(lp00, lp01));
            __stcs(lp1 + (cc >> 1), make_float2(lp10, lp11));
            m0 = fmaxf(m0, fmaxf(lp00 + la0, lp01 + la1));
            m1 = fmaxf(m1, fmaxf(lp10 + la0, lp11 + la1));
        }
        m0 = fmaxf(m0, __shfl_xor_sync(0xffffffffu, m0, 1));
        m0 = fmaxf(m0, __shfl_xor_sync(0xffffffffu, m0, 2));
        m1 = fmaxf(m1, __shfl_xor_sync(0xffffffffu, m1, 1));
        m1 = fmaxf(m1, __shfl_xor_sync(0xffffffffu, m1, 2));

        float s0 = 0.0f, s1 = 0.0f;
#pragma unroll
        for (int t = 0; t < 8; t++) {
            int cc = t * 8 + cq;
            float a0 = G ? acc1[t][0] : acc0[t][0];
            float a1 = G ? acc1[t][1] : acc0[t][1];
            float a2 = G ? acc1[t][2] : acc0[t][2];
            float a3 = G ? acc1[t][3] : acc0[t][3];
            float k0 = s_kappa[cc], k1 = s_kappa[cc + 1];
            float c20 = s_C2[cc],   c21 = s_C2[cc + 1];
            s0 += fexp(fmaf(k0, a0, c20) - m0);
            s0 += fexp(fmaf(k1, a1, c21) - m0);
            s1 += fexp(fmaf(k0, a2, c20) - m1);
            s1 += fexp(fmaf(k1, a3, c21) - m1);
        }
        s0 += __shfl_xor_sync(0xffffffffu, s0, 1);
        s0 += __shfl_xor_sync(0xffffffffu, s0, 2);
        s1 += __shfl_xor_sync(0xffffffffu, s1, 1);
        s1 += __shfl_xor_sync(0xffffffffu, s1, 2);

        if ((lane & 3) == 0) {
            out_llh[gr0] = m0 + __logf(s0);
            out_llh[gr1] = m1 + __logf(s1);
        }
    }
}

// ---------------- launch: prep -> main with programmatic dependent launch -------------
extern "C" void kernel_launch(void* const* d_in, const int* in_sizes, int n_in,
                              void* d_out, int out_size) {
    const float* x           = (const float*)d_in[0];
    const float* alpha_logit = (const float*)d_in[1];
    const float* mu_unnorm   = (const float*)d_in[2];
    const float* log_kappa   = (const float*)d_in[3];

    int K = in_sizes[1];            // 64
    int D = in_sizes[2] / K;        // 256
    int N = in_sizes[0] / D;        // 262144
    (void)n_in; (void)out_size;

    float* out = (float*)d_out;
    float* llh = out;               // (N,)
    float* lp  = out + (size_t)N;   // (N, K)

    prep_fast<<<K_COMP, 128>>>(alpha_logit, mu_unnorm, log_kappa);

    cudaLaunchConfig_t cfg = {};
    cfg.gridDim  = dim3(N / 256, 1, 1);
    cfg.blockDim = dim3(256, 1, 1);
    cfg.dynamicSmemBytes = 0;
    cudaLaunchAttribute attrs[1];
    attrs[0].id = cudaLaunchAttributeProgrammaticStreamSerialization;
    attrs[0].val.programmaticStreamSerializationAllowed = 1;
    cfg.attrs = attrs;
    cfg.numAttrs = 1;
    cudaLaunchKernelEx(&cfg, vmf_main, x, llh, lp, N);
}

// round 16
// speedup vs baseline: 1.1702x; 1.0257x over previous
#include <cuda_runtime.h>
#include <cuda_bf16.h>
#include <math.h>
#include <stdint.h>

#define K_COMP 64
#define DDIM   256
#define MU_PAD 264     // bf16/row: 132 words -> ldmatrix rows cover all 32 banks

__device__ __align__(16) __nv_bfloat16 g_mu[K_COMP * DDIM];
__device__ float g_kappa[K_COMP];
__device__ float g_logC[K_COMP];
__device__ float g_la[K_COMP];
__device__ float g_C2[K_COMP];

// ---------------- prep: 64 blocks (one per component); triggers PDL at end ------------
__global__ void prep_fast(const float* __restrict__ alpha_logit,
                          const float* __restrict__ mu_unnorm,
                          const float* __restrict__ log_kappa) {
    __shared__ float sred[4];
    int k = blockIdx.x;
    int tid = threadIdx.x, lane = tid & 31, w = tid >> 5;
    const float s = 0.5f * (float)DDIM - 1.0f;   // 127

    float2 v = reinterpret_cast<const float2*>(mu_unnorm + (size_t)k * DDIM)[tid];
    float ss = v.x * v.x + v.y * v.y;
#pragma unroll
    for (int o = 16; o; o >>= 1) ss += __shfl_xor_sync(0xffffffffu, ss, o);
    if (lane == 0) sred[w] = ss;
    __syncthreads();
    float tot = sred[0] + sred[1] + sred[2] + sred[3];
    float inv = 1.0f / fmaxf(sqrtf(tot), 1e-12f);
    reinterpret_cast<__nv_bfloat162*>(g_mu + (size_t)k * DDIM)[tid] =
        __float22bfloat162_rn(make_float2(v.x * inv, v.y * inv));

    if (w == 0) {
        float a0 = alpha_logit[lane], a1 = alpha_logit[lane + 32];
        float am = fmaxf(a0, a1);
#pragma unroll
        for (int o = 16; o; o >>= 1) am = fmaxf(am, __shfl_xor_sync(0xffffffffu, am, o));
        float ae = expf(a0 - am) + expf(a1 - am);
#pragma unroll
        for (int o = 16; o; o >>= 1) ae += __shfl_xor_sync(0xffffffffu, ae, o);
        float lse = am + logf(ae);

        float kap = expf(log_kappa[k]) + 1e-6f;
        float lk2 = logf(0.5f * kap);
        float cm0 = lgammaf((float)lane + 1.0f)  + lgammaf((float)lane + s + 1.0f);
        float cm1 = lgammaf((float)lane + 33.0f) + lgammaf((float)lane + s + 33.0f);
        float t0 = fmaf(2.0f * lane + s,        lk2, -cm0);
        float t1 = fmaf(2.0f * (lane + 32) + s, lk2, -cm1);
        float tm = fmaxf(t0, t1);
#pragma unroll
        for (int o = 16; o; o >>= 1) tm = fmaxf(tm, __shfl_xor_sync(0xffffffffu, tm, o));
        float ts = expf(t0 - tm) + expf(t1 - tm);
#pragma unroll
        for (int o = 16; o; o >>= 1) ts += __shfl_xor_sync(0xffffffffu, ts, o);

        if (lane == 0) {
            float lbi  = tm + logf(ts);
            float logC = (float)DDIM * (-0.91893853320467274f) + s * logf(kap) - lbi;
            float la   = alpha_logit[k] - lse;
            g_kappa[k] = kap;
            g_logC[k]  = logC;
            g_la[k]    = la;
            g_C2[k]    = logC + la;
        }
    }
    __syncthreads();   // all writes done before trigger
    cudaTriggerProgrammaticLaunchCompletion();
}

// ---------------- fast exp: FFMA-only ----------------
__device__ __forceinline__ float fexp(float x) {
    x = fmaxf(x, -87.0f);
    float z = x * 1.4426950408889634f;
    float t = z + 12582912.0f;
    float fi = t - 12582912.0f;
    float f = z - fi;
    int  i  = __float_as_int(t) - 0x4B400000;
    float p = 1.3333558e-3f;
    p = fmaf(p, f, 9.6181291e-3f);
    p = fmaf(p, f, 5.5504109e-2f);
    p = fmaf(p, f, 2.4022651e-1f);
    p = fmaf(p, f, 6.9314718e-1f);
    p = fmaf(p, f, 1.0f);
    return __int_as_float(__float_as_int(p) + (i << 23));
}

__device__ __forceinline__ uint32_t f22bf(float2 v) {
    __nv_bfloat162 b = __float22bfloat162_rn(v);
    return *reinterpret_cast<uint32_t*>(&b);
}

// ---------------- main: R10 + PDL, with x prefetch issued BEFORE the dependency sync --
// The initial 8 __ldcs (prep-independent) go out before cudaGridDependencySynchronize,
// so first-wave CTAs pull x from DRAM concurrently with prep's execution and hide the
// ~600cy initial load chain under the PDL window.
__global__ void __launch_bounds__(256, 2)
vmf_main(const float* __restrict__ x,
         float* __restrict__ out_llh,
         float* __restrict__ out_lp,
         int N) {
    __shared__ __align__(16) __nv_bfloat16 smu[K_COMP][MU_PAD];
    __shared__ float s_kappa[K_COMP], s_logC[K_COMP], s_la[K_COMP], s_C2[K_COMP];

    int tid = threadIdx.x;
    int warp = tid >> 5, lane = tid & 31;
    int row0 = blockIdx.x * 256 + warp * 32;   // 32 rows per warp
    int r  = lane >> 2;        // 0..7
    int cq = (lane & 3) * 2;   // logical col-pair base (epilogue)

    const float* p0 = x + (size_t)(row0 + r) * DDIM + (lane & 3) * 4;

    // ---- prep-independent work FIRST: prime the x prefetch pipeline ----
    float4 buf[2][4];
#pragma unroll
    for (int c = 0; c < 2; c++)
#pragma unroll
        for (int g = 0; g < 4; g++)
            buf[c][g] = __ldcs(reinterpret_cast<const float4*>(p0 + c * 16 + g * 8 * DDIM));

    uint32_t smu_base = (uint32_t)__cvta_generic_to_shared(&smu[0][0]);
    int li   = lane & 7;
    int csel = (lane >> 3) & 1;
    int tsel = (lane >> 4) & 1;
    uint32_t lm_base = smu_base + (uint32_t)(((li + tsel * 8) * MU_PAD + csel * 8) * 2);

    float acc0[8][4], acc1[8][4];
#pragma unroll
    for (int t = 0; t < 8; t++)
#pragma unroll
        for (int j = 0; j < 4; j++) { acc0[t][j] = 0.0f; acc1[t][j] = 0.0f; }

    // ---- now wait for prep's g_* writes (overlapped with the loads above) ----
    cudaGridDependencySynchronize();

    // stage mu with k-pair permutation (slot i <- phys pair (i<4 ? 2i : 2i-7))
    const uint32_t* gmu32 = reinterpret_cast<const uint32_t*>(g_mu);
    for (int idx = tid; idx < K_COMP * (DDIM / 2); idx += 256) {
        int kk = idx >> 7;
        int dp = idx & 127;
        int i  = dp & 7;
        int srcp = (i < 4) ? (2 * i) : (2 * i - 7);
        int src  = (dp & ~7) | srcp;
        reinterpret_cast<uint32_t*>(&smu[kk][0])[dp] = gmu32[kk * 128 + src];
    }
    if (tid < K_COMP) {
        s_kappa[tid] = g_kappa[tid];
        s_logC[tid]  = g_logC[tid];
        s_la[tid]    = g_la[tid];
        s_C2[tid]    = g_C2[tid];
    }
    __syncthreads();

#pragma unroll
    for (int kk = 0; kk < 16; kk++) {
        int b = kk & 1;
        float4 A0 = buf[b][0], A1 = buf[b][1], A2 = buf[b][2], A3 = buf[b][3];

        uint32_t u0 = f22bf(make_float2(A0.x, A0.y));
        uint32_t u1 = f22bf(make_float2(A1.x, A1.y));
        uint32_t u2 = f22bf(make_float2(A0.z, A0.w));
        uint32_t u3 = f22bf(make_float2(A1.z, A1.w));
        uint32_t v0 = f22bf(make_float2(A2.x, A2.y));
        uint32_t v1 = f22bf(make_float2(A3.x, A3.y));
        uint32_t v2 = f22bf(make_float2(A2.z, A2.w));
        uint32_t v3 = f22bf(make_float2(A3.z, A3.w));

        if (kk < 14) {
            int off = (kk + 2) * 16;
#pragma unroll
            for (int g = 0; g < 4; g++)
                buf[b][g] = __ldcs(reinterpret_cast<const float4*>(p0 + off + g * 8 * DDIM));
        }

        uint32_t lmaddr = lm_base + (uint32_t)(kk * 32);
#pragma unroll
        for (int tp = 0; tp < 4; tp++) {
            uint32_t b0, b1, b2, b3;
            asm volatile(
                "ldmatrix.sync.aligned.m8n8.x4.shared.b16 {%0,%1,%2,%3}, [%4];\n"
                : "=r"(b0), "=r"(b1), "=r"(b2), "=r"(b3)
                : "r"(lmaddr + (uint32_t)(tp * 16 * MU_PAD * 2)));
            asm volatile(
                "mma.sync.aligned.m16n8k16.row.col.f32.bf16.bf16.f32 "
                "{%0,%1,%2,%3}, {%4,%5,%6,%7}, {%8,%9}, {%0,%1,%2,%3};\n"
                : "+f"(acc0[tp*2][0]), "+f"(acc0[tp*2][1]), "+f"(acc0[tp*2][2]), "+f"(acc0[tp*2][3])
                : "r"(u0), "r"(u1), "r"(u2), "r"(u3), "r"(b0), "r"(b1));
            asm volatile(
                "mma.sync.aligned.m16n8k16.row.col.f32.bf16.bf16.f32 "
                "{%0,%1,%2,%3}, {%4,%5,%6,%7}, {%8,%9}, {%0,%1,%2,%3};\n"
                : "+f"(acc0[tp*2+1][0]), "+f"(acc0[tp*2+1][1]), "+f"(acc0[tp*2+1][2]), "+f"(acc0[tp*2+1][3])
                : "r"(u0), "r"(u1), "r"(u2), "r"(u3), "r"(b2), "r"(b3));
            asm volatile(
                "mma.sync.aligned.m16n8k16.row.col.f32.bf16.bf16.f32 "
                "{%0,%1,%2,%3}, {%4,%5,%6,%7}, {%8,%9}, {%0,%1,%2,%3};\n"
                : "+f"(acc1[tp*2][0]), "+f"(acc1[tp*2][1]), "+f"(acc1[tp*2][2]), "+f"(acc1[tp*2][3])
                : "r"(v0), "r"(v1), "r"(v2), "r"(v3), "r"(b0), "r"(b1));
            asm volatile(
                "mma.sync.aligned.m16n8k16.row.col.f32.bf16.bf16.f32 "
                "{%0,%1,%2,%3}, {%4,%5,%6,%7}, {%8,%9}, {%0,%1,%2,%3};\n"
                : "+f"(acc1[tp*2+1][0]), "+f"(acc1[tp*2+1][1]), "+f"(acc1[tp*2+1][2]), "+f"(acc1[tp*2+1][3])
                : "r"(v0), "r"(v1), "r"(v2), "r"(v3), "r"(b2), "r"(b3));
        }
    }

    // ---- epilogue: two row-groups, R4 form each ----
#pragma unroll
    for (int G = 0; G < 2; G++) {
        int gr0 = row0 + G * 16 + r, gr1 = gr0 + 8;
        float2* lp0 = reinterpret_cast<float2*>(out_lp + (size_t)gr0 * K_COMP);
        float2* lp1 = reinterpret_cast<float2*>(out_lp + (size_t)gr1 * K_COMP);

        float m0 = -1e30f, m1 = -1e30f;
#pragma unroll
        for (int t = 0; t < 8; t++) {
            int cc = t * 8 + cq;
            float a0 = G ? acc1[t][0] : acc0[t][0];
            float a1 = G ? acc1[t][1] : acc0[t][1];
            float a2 = G ? acc1[t][2] : acc0[t][2];
            float a3 = G ? acc1[t][3] : acc0[t][3];
            float k0 = s_kappa[cc], k1 = s_kappa[cc + 1];
            float lc0 = s_logC[cc], lc1 = s_logC[cc + 1];
            float la0 = s_la[cc],   la1 = s_la[cc + 1];
            float lp00 = fmaf(k0, a0, lc0);
            float lp01 = fmaf(k1, a1, lc1);
            float lp10 = fmaf(k0, a2, lc0);
            float lp11 = fmaf(k1, a3, lc1);
            __stcs(lp0 + (cc >> 1), make_float2(lp00, lp01));
            __stcs(lp1 + (cc >> 1), make_float2(lp10, lp11));
            m0 = fmaxf(m0, fmaxf(lp00 + la0, lp01 + la1));
            m1 = fmaxf(m1, fmaxf(lp10 + la0, lp11 + la1));
        }
        m0 = fmaxf(m0, __shfl_xor_sync(0xffffffffu, m0, 1));
        m0 = fmaxf(m0, __shfl_xor_sync(0xffffffffu, m0, 2));
        m1 = fmaxf(m1, __shfl_xor_sync(0xffffffffu, m1, 1));
        m1 = fmaxf(m1, __shfl_xor_sync(0xffffffffu, m1, 2));

        float s0 = 0.0f, s1 = 0.0f;
#pragma unroll
        for (int t = 0; t < 8; t++) {
            int cc = t * 8 + cq;
            float a0 = G ? acc1[t][0] : acc0[t][0];
            float a1 = G ? acc1[t][1] : acc0[t][1];
            float a2 = G ? acc1[t][2] : acc0[t][2];
            float a3 = G ? acc1[t][3] : acc0[t][3];
            float k0 = s_kappa[cc], k1 = s_kappa[cc + 1];
            float c20 = s_C2[cc],   c21 = s_C2[cc + 1];
            s0 += fexp(fmaf(k0, a0, c20) - m0);
            s0 += fexp(fmaf(k1, a1, c21) - m0);
            s1 += fexp(fmaf(k0, a2, c20) - m1);
            s1 += fexp(fmaf(k1, a3, c21) - m1);
        }
        s0 += __shfl_xor_sync(0xffffffffu, s0, 1);
        s0 += __shfl_xor_sync(0xffffffffu, s0, 2);
        s1 += __shfl_xor_sync(0xffffffffu, s1, 1);
        s1 += __shfl_xor_sync(0xffffffffu, s1, 2);

        if ((lane & 3) == 0) {
            out_llh[gr0] = m0 + __logf(s0);
            out_llh[gr1] = m1 + __logf(s1);
        }
    }
}

// ---------------- launch: prep -> main with programmatic dependent launch -------------
extern "C" void kernel_launch(void* const* d_in, const int* in_sizes, int n_in,
                              void* d_out, int out_size) {
    const float* x           = (const float*)d_in[0];
    const float* alpha_logit = (const float*)d_in[1];
    const float* mu_unnorm   = (const float*)d_in[2];
    const float* log_kappa   = (const float*)d_in[3];

    int K = in_sizes[1];            // 64
    int D = in_sizes[2] / K;        // 256
    int N = in_sizes[0] / D;        // 262144
    (void)n_in; (void)out_size;

    float* out = (float*)d_out;
    float* llh = out;               // (N,)
    float* lp  = out + (size_t)N;   // (N, K)

    prep_fast<<<K_COMP, 128>>>(alpha_logit, mu_unnorm, log_kappa);

    cudaLaunchConfig_t cfg = {};
    cfg.gridDim  = dim3(N / 256, 1, 1);
    cfg.blockDim = dim3(256, 1, 1);
    cfg.dynamicSmemBytes = 0;
    cudaLaunchAttribute attrs[1];
    attrs[0].id = cudaLaunchAttributeProgrammaticStreamSerialization;
    attrs[0].val.programmaticStreamSerializationAllowed = 1;
    cfg.attrs = attrs;
    cfg.numAttrs = 1;
    cudaLaunchKernelEx(&cfg, vmf_main, x, llh, lp, N);
}